// round 15
// baseline (speedup 1.0000x reference)
#include <cuda_runtime.h>
#include <math.h>

#define BT 512   // threads per block (main kernel)
#define M  8     // batch rows per block

// ---------------- problem constants ----------------
constexpr int Bsz = 1024, Tsz = 256, DIN = 128;
constexpr int NH0 = 269, NH1 = 179, NH2 = 64;
constexpr int CAT0 = DIN + NH0;   // 397
constexpr int CAT1 = NH0 + NH1;   // 448
constexpr int CAT2 = NH1 + NH2;   // 243
constexpr int CATP0 = 400, CATP1 = 448, CATP2 = 244;
constexpr int NIN0 = 128, NIN1 = 269, NIN2 = 179;     // masked input region
constexpr int NREC0 = 269, NREC1 = 179, NREC2 = 64;   // dense recurrent region
constexpr int OUTD = 64;
constexpr long long PRED_ELEMS = (long long)Bsz * Tsz * OUTD;

// ---------------- device scratch ----------------
// ta (=wa+wb) dense k-major [k][j]
__device__ float g_TA0[CATP0 * NH0];
__device__ float g_TA1[CATP1 * NH1];
__device__ float g_TA2[CATP2 * NH2];
// ff1/ff2 recurrent region dense [k'][j]
__device__ float g_F1R0[NREC0 * NH0], g_F2R0[NREC0 * NH0];
__device__ float g_F1R1[NREC1 * NH1], g_F2R1[NREC1 * NH1];
__device__ float g_F1R2[NREC2 * NH2], g_F2R2[NREC2 * NH2];
// ff1/ff2 input region packed: [slot][j], per-j count in g_CNT*
__device__ float    g_P10[NIN0 * NH0], g_P20[NIN0 * NH0];
__device__ unsigned g_PO0[NIN0 * NH0];
__device__ float    g_P11[NIN1 * NH1], g_P21[NIN1 * NH1];
__device__ unsigned g_PO1[NIN1 * NH1];
__device__ float    g_P12[NIN2 * NH2], g_P22[NIN2 * NH2];
__device__ unsigned g_PO2[NIN2 * NH2];
__device__ unsigned g_CNT0[NH0], g_CNT1[NH1], g_CNT2[NH2];
// biases (3 per layer: ff1, ff2, ta=ba+bb)
__device__ float g_B0[3 * NH0];
__device__ float g_B1[3 * NH1];
__device__ float g_B2[3 * NH2];
__device__ int   g_fmt[3];

// ---------------- mask dtype detection (unchanged, known-good) ----------------
__global__ void detect_kernel(const void* m0, int n0, const void* m1, int n1,
                              const void* m2, int n2) {
    const void* p = (blockIdx.x == 0) ? m0 : (blockIdx.x == 1) ? m1 : m2;
    int n = (blockIdx.x == 0) ? n0 : (blockIdx.x == 1) ? n1 : n2;
    __shared__ int fl;
    if (threadIdx.x == 0) fl = 0;
    __syncthreads();
    int nw = n >> 2;
    const unsigned* w = (const unsigned*)p;
    int loc = 0;
    for (int i = threadIdx.x; i < nw; i += blockDim.x) {
        unsigned v = w[i];
        if (v == 0x3F800000u) loc |= 1;
        else if (v == 0x3F803F80u || v == 0x00003F80u) loc |= 2;
        else if (v != 0u && v != 1u) loc |= 4;
    }
    atomicOr(&fl, loc);
    __syncthreads();
    if (threadIdx.x == 0) {
        int f = fl, fmt;
        if (f & 2) fmt = 3;
        else if (f & 1) fmt = 0;
        else if (f & 4) fmt = 2;
        else fmt = 1;
        g_fmt[blockIdx.x] = fmt;
    }
}

__device__ __forceinline__ bool maskbit(const void* p, int fmt, int idx) {
    switch (fmt) {
        case 0: return ((const float*)p)[idx] != 0.0f;
        case 1: return ((const int*)p)[idx] != 0;
        case 3: return ((const unsigned short*)p)[idx] != 0;
        default: return ((const unsigned char*)p)[idx] != 0;
    }
}

// ---------------- prep: dense parts (ta, ff-recurrent, biases) ----------------
__device__ __forceinline__ void dense_elem(
    long long idx, int CAT, int CATP, int NH, int NIN, int NREC,
    const float* w1, const float* w2, const float* wa, const float* wb,
    const float* b1, const float* b2, const float* ba, const float* bb,
    float* TA, float* F1R, float* F2R, float* Bc) {
    long long sTA = (long long)CATP * NH;
    if (idx < sTA) {
        int k = (int)(idx / NH), j = (int)(idx - (long long)k * NH);
        float v = 0.0f;
        if (k < CAT) v = wa[j * CAT + k] + wb[j * CAT + k];
        TA[idx] = v;
        if (k == 0) {
            Bc[j] = b1[j]; Bc[NH + j] = b2[j]; Bc[2 * NH + j] = ba[j] + bb[j];
        }
    } else {
        long long r = idx - sTA;
        long long per = (long long)NREC * NH;
        int g = (int)(r / per);
        long long r2 = r - (long long)g * per;
        int kp = (int)(r2 / NH), j = (int)(r2 - (long long)kp * NH);
        const float* w = g ? w2 : w1;
        float v = w[j * CAT + NIN + kp];      // recurrent region: mask == 1
        (g ? F2R : F1R)[r2] = v;
    }
}

__global__ void prep_dense(
    const float* f10, const float* f20, const float* ta0, const float* tb0,
    const float* b10, const float* b20, const float* ba0, const float* bb0,
    const float* f11, const float* f21, const float* ta1, const float* tb1,
    const float* b11, const float* b21, const float* ba1, const float* bb1,
    const float* f12, const float* f22, const float* ta2, const float* tb2,
    const float* b12, const float* b22, const float* ba2, const float* bb2) {
    const long long S0 = (long long)CATP0 * NH0 + 2LL * NREC0 * NH0;
    const long long S1 = (long long)CATP1 * NH1 + 2LL * NREC1 * NH1;
    const long long S2 = (long long)CATP2 * NH2 + 2LL * NREC2 * NH2;
    const long long total = S0 + S1 + S2;
    for (long long idx = (long long)blockIdx.x * blockDim.x + threadIdx.x;
         idx < total; idx += (long long)gridDim.x * blockDim.x) {
        if (idx < S0)
            dense_elem(idx, CAT0, CATP0, NH0, NIN0, NREC0,
                       f10, f20, ta0, tb0, b10, b20, ba0, bb0,
                       g_TA0, g_F1R0, g_F2R0, g_B0);
        else if (idx < S0 + S1)
            dense_elem(idx - S0, CAT1, CATP1, NH1, NIN1, NREC1,
                       f11, f21, ta1, tb1, b11, b21, ba1, bb1,
                       g_TA1, g_F1R1, g_F2R1, g_B1);
        else
            dense_elem(idx - S0 - S1, CAT2, CATP2, NH2, NIN2, NREC2,
                       f12, f22, ta2, tb2, b12, b22, ba2, bb2,
                       g_TA2, g_F1R2, g_F2R2, g_B2);
    }
}

// ---------------- prep: pack input-region ff weights per output j ------------
__device__ __forceinline__ void pack_one(
    const float* w1, const float* w2, const void* mask, int fmt,
    int CAT, int NIN, int NH, int j,
    float* P1, float* P2, unsigned* PO, unsigned* CNT) {
    int s = 0;
    for (int k = 0; k < NIN; ++k) {
        if (maskbit(mask, fmt, j * CAT + k)) {
            P1[(size_t)s * NH + j] = w1[j * CAT + k];
            P2[(size_t)s * NH + j] = w2[j * CAT + k];
            PO[(size_t)s * NH + j] = (unsigned)(k * M * 4);  // byte offset into xt
            ++s;
        }
    }
    CNT[j] = (unsigned)s;
}

__global__ void prep_pack(
    const float* f10, const float* f20, const void* m0,
    const float* f11, const float* f21, const void* m1,
    const float* f12, const float* f22, const void* m2) {
    int t = threadIdx.x;
    if (t < NH0)
        pack_one(f10, f20, m0, g_fmt[0], CAT0, NIN0, NH0, t,
                 g_P10, g_P20, g_PO0, g_CNT0);
    else if (t < NH0 + NH1)
        pack_one(f11, f21, m1, g_fmt[1], CAT1, NIN1, NH1, t - NH0,
                 g_P11, g_P21, g_PO1, g_CNT1);
    else if (t < NH0 + NH1 + NH2)
        pack_one(f12, f22, m2, g_fmt[2], CAT2, NIN2, NH2, t - NH0 - NH1,
                 g_P12, g_P22, g_PO2, g_CNT2);
}

// ---------------- main persistent kernel ----------------
struct SM {
    float xt0[2][CATP0][M];       // [buf][ x(128) | h0(269) | pad ]
    float xt1[CATP1][M];          // [ n0(269) | h1(179) ]
    float xt2[CATP2][M];          // [ n1(179) | h2(64) | pad ]
    union {
        struct { float m[2][256][3][M]; float x[16][13][3][M]; } p0;
        float p1[7][NH1][3][M];
        float p2[8][64][3][M];
    } P;
    float fcT[OUTD * OUTD];
    float fcb[OUTD];
    float b0[3 * NH0];
    float b1[3 * NH1];
    float b2[3 * NH2];
    unsigned c0[NH0];
    unsigned c1[NH1];
    unsigned c2[NH2];
};

#define FMA8(acc, WV)                                                          \
    acc[0] += (WV) * xa.x; acc[1] += (WV) * xa.y;                              \
    acc[2] += (WV) * xa.z; acc[3] += (WV) * xa.w;                              \
    acc[4] += (WV) * xb.x; acc[5] += (WV) * xb.y;                              \
    acc[6] += (WV) * xb.z; acc[7] += (WV) * xb.w;

// C-loop: all 3 gates over recurrent region k' in [k0, k0+klen)
template <int NH>
__device__ __forceinline__ void gemm_rec(
    const float* __restrict__ F1, const float* __restrict__ F2,
    const float* __restrict__ TA, int NIN, int j, int k0, int klen,
    const float (*__restrict__ xt)[M],
    float* __restrict__ a1, float* __restrict__ a2, float* __restrict__ a3) {
    const float* p1 = F1 + (size_t)k0 * NH + j;
    const float* p2 = F2 + (size_t)k0 * NH + j;
    const float* p3 = TA + (size_t)(NIN + k0) * NH + j;
    const float* xp = &xt[NIN + k0][0];
#pragma unroll 4
    for (int k = 0; k < klen; ++k) {
        float w1 = __ldg(p1), w2 = __ldg(p2), w3 = __ldg(p3);
        float4 xa = *(const float4*)xp;
        float4 xb = *(const float4*)(xp + 4);
        p1 += NH; p2 += NH; p3 += NH; xp += M;
        FMA8(a1, w1); FMA8(a2, w2); FMA8(a3, w3);
    }
}

// A-loop: ta only over input region k in [k0, k0+klen)
template <int NH>
__device__ __forceinline__ void gemm_ta(
    const float* __restrict__ TA, int j, int k0, int klen,
    const float (*__restrict__ xt)[M], float* __restrict__ a3) {
    const float* p3 = TA + (size_t)k0 * NH + j;
    const float* xp = &xt[k0][0];
#pragma unroll 4
    for (int k = 0; k < klen; ++k) {
        float w3 = __ldg(p3);
        float4 xa = *(const float4*)xp;
        float4 xb = *(const float4*)(xp + 4);
        p3 += NH; xp += M;
        FMA8(a3, w3);
    }
}

// B-loop: packed ff1/ff2 over slots [s0, s1)
template <int NH>
__device__ __forceinline__ void gemm_pk(
    const float* __restrict__ P1, const float* __restrict__ P2,
    const unsigned* __restrict__ PO, int j, int s0, int s1,
    const float* __restrict__ xb0,
    float* __restrict__ a1, float* __restrict__ a2) {
    const float* p1 = P1 + (size_t)s0 * NH + j;
    const float* p2 = P2 + (size_t)s0 * NH + j;
    const unsigned* po = PO + (size_t)s0 * NH + j;
#pragma unroll 4
    for (int s = s0; s < s1; ++s) {
        float w1 = __ldg(p1), w2 = __ldg(p2);
        unsigned off = __ldg(po);
        const float* xp = (const float*)((const char*)xb0 + off);
        float4 xa = *(const float4*)xp;
        float4 xb = *(const float4*)(xp + 4);
        p1 += NH; p2 += NH; po += NH;
        FMA8(a1, w1); FMA8(a2, w2);
    }
}

__device__ __forceinline__ float cfc_cell(float f1, float f2, float g3) {
    float s = 1.0f / (1.0f + __expf(-g3));
    return tanhf(f1) * (1.0f - s) + s * tanhf(f2);
}

__device__ __forceinline__ void store_part(float (*__restrict__ P)[M],
                                           const float* a1, const float* a2,
                                           const float* a3) {
    *(float4*)&P[0][0] = make_float4(a1[0], a1[1], a1[2], a1[3]);
    *(float4*)&P[0][4] = make_float4(a1[4], a1[5], a1[6], a1[7]);
    *(float4*)&P[1][0] = make_float4(a2[0], a2[1], a2[2], a2[3]);
    *(float4*)&P[1][4] = make_float4(a2[4], a2[5], a2[6], a2[7]);
    *(float4*)&P[2][0] = make_float4(a3[0], a3[1], a3[2], a3[3]);
    *(float4*)&P[2][4] = make_float4(a3[4], a3[5], a3[6], a3[7]);
}

__global__ __launch_bounds__(BT, 1)
void ncp_main(const float* __restrict__ x, const float* __restrict__ hidden,
              const float* __restrict__ fc_w, const float* __restrict__ fc_b,
              float* __restrict__ out) {
    extern __shared__ char smem_raw[];
    SM* sm = (SM*)smem_raw;
    const int tid = threadIdx.x;
    const int row0 = blockIdx.x * M;
    const int xr = tid & 7, xc = tid >> 3;   // x prefetch mapping (xc 0..63)

    // ---- init ----
    for (int i = tid; i < 3 * NH0; i += BT) sm->b0[i] = g_B0[i];
    for (int i = tid; i < 3 * NH1; i += BT) sm->b1[i] = g_B1[i];
    for (int i = tid; i < 3 * NH2; i += BT) sm->b2[i] = g_B2[i];
    for (int i = tid; i < NH0; i += BT) sm->c0[i] = g_CNT0[i];
    for (int i = tid; i < NH1; i += BT) sm->c1[i] = g_CNT1[i];
    for (int i = tid; i < NH2; i += BT) sm->c2[i] = g_CNT2[i];
    for (int i = tid; i < OUTD * OUTD; i += BT) {
        int mm = i >> 6, o = i & 63;
        sm->fcT[i] = __ldg(&fc_w[o * OUTD + mm]);
    }
    if (tid < OUTD) sm->fcb[tid] = fc_b[tid];
    for (int i = tid; i < M * 512; i += BT) {
        int r = i >> 9, c = i & 511;
        float v = hidden[(long long)(row0 + r) * 512 + c];
        if (c < NH0)              sm->xt0[0][DIN + c][r] = v;
        else if (c < NH0 + NH1)   sm->xt1[c][r] = v;
        else                      sm->xt2[NH1 + (c - NH0 - NH1)][r] = v;
    }
    if (tid < M) {
        sm->xt0[0][397][tid] = 0.0f; sm->xt0[0][398][tid] = 0.0f; sm->xt0[0][399][tid] = 0.0f;
        sm->xt0[1][397][tid] = 0.0f; sm->xt0[1][398][tid] = 0.0f; sm->xt0[1][399][tid] = 0.0f;
        sm->xt2[243][tid] = 0.0f;
    }
    // preload x(0)
    {
        const float* xp = x + ((long long)(row0 + xr) * Tsz + 0) * DIN;
        sm->xt0[0][xc][xr]      = __ldg(&xp[xc]);
        sm->xt0[0][xc + 64][xr] = __ldg(&xp[xc + 64]);
    }
    __syncthreads();

    // ---- sequential timestep loop ----
#pragma unroll 1
    for (int t = 0; t < Tsz; ++t) {
        const int b = t & 1, nb = b ^ 1;

        // prefetch x(t+1) into registers (stored in FC phase)
        float rx0 = 0.f, rx1 = 0.f;
        if (t + 1 < Tsz) {
            const float* xp = x + ((long long)(row0 + xr) * Tsz + (t + 1)) * DIN;
            rx0 = __ldg(&xp[xc]);
            rx1 = __ldg(&xp[xc + 64]);
        }

        // ===== layer 0 gemm =====
        {
            const int jj = tid & 255, h = tid >> 8;
            float a1[M], a2[M], a3[M];
#pragma unroll
            for (int r = 0; r < M; ++r) { a1[r] = 0.f; a2[r] = 0.f; a3[r] = 0.f; }
            if (h == 0) {
                gemm_rec<NH0>(g_F1R0, g_F2R0, g_TA0, NIN0, jj, 0, 182,
                              sm->xt0[b], a1, a2, a3);
            } else {
                gemm_rec<NH0>(g_F1R0, g_F2R0, g_TA0, NIN0, jj, 182, 87,
                              sm->xt0[b], a1, a2, a3);
                gemm_ta<NH0>(g_TA0, jj, 0, 128, sm->xt0[b], a3);
                gemm_pk<NH0>(g_P10, g_P20, g_PO0, jj, 0, (int)sm->c0[jj],
                             &sm->xt0[b][0][0], a1, a2);
            }
            store_part(sm->P.p0.m[h][jj], a1, a2, a3);
        }
        // L0 tail: j = 256..268 flattened into 208 chunk-units on tids 304..511
        if (tid >= 304) {
            int w = tid - 304;
            float t1[M], t2[M], t3[M];
#pragma unroll
            for (int r = 0; r < M; ++r) { t1[r] = 0.f; t2[r] = 0.f; t3[r] = 0.f; }
            int ju, slot;
            if (w < 156) {                       // C chunks: 12 per j
                ju = w % 13; int cc = w / 13;
                int k0 = cc * 23, len = min(23, 269 - k0);
                gemm_rec<NH0>(g_F1R0, g_F2R0, g_TA0, NIN0, 256 + ju, k0, len,
                              sm->xt0[b], t1, t2, t3);
                slot = cc;
            } else if (w < 182) {                // A halves: 2 per j
                int w2 = w - 156; ju = w2 % 13; int hf = w2 / 13;
                gemm_ta<NH0>(g_TA0, 256 + ju, hf * 64, 64, sm->xt0[b], t3);
                slot = 12 + hf;
            } else {                             // B slot-halves: 2 per j
                int w3 = w - 182; ju = w3 % 13; int hf = w3 / 13;
                int cnt = (int)sm->c0[256 + ju];
                int s0 = hf ? 40 : 0;
                int s1 = hf ? cnt : min(40, cnt);
                gemm_pk<NH0>(g_P10, g_P20, g_PO0, 256 + ju, s0, s1,
                             &sm->xt0[b][0][0], t1, t2);
                slot = 14 + hf;
            }
            store_part(sm->P.p0.x[slot][ju], t1, t2, t3);
        }
        __syncthreads();

        // ===== layer 0 reduce + bias + activate =====
        for (int c = tid; c < NH0 * M; c += BT) {
            int j = c >> 3, r = c & 7;
            float f1, f2, g3;
            if (j < 256) {
                f1 = sm->P.p0.m[0][j][0][r] + sm->P.p0.m[1][j][0][r];
                f2 = sm->P.p0.m[0][j][1][r] + sm->P.p0.m[1][j][1][r];
                g3 = sm->P.p0.m[0][j][2][r] + sm->P.p0.m[1][j][2][r];
            } else {
                int ju = j - 256;
                f1 = 0.f; f2 = 0.f; g3 = 0.f;
#pragma unroll
                for (int sl = 0; sl < 16; ++sl) {
                    f1 += sm->P.p0.x[sl][ju][0][r];
                    f2 += sm->P.p0.x[sl][ju][1][r];
                    g3 += sm->P.p0.x[sl][ju][2][r];
                }
            }
            f1 += sm->b0[j]; f2 += sm->b0[NH0 + j]; g3 += sm->b0[2 * NH0 + j];
            float n = cfc_cell(f1, f2, g3);
            sm->xt1[j][r] = n;
            sm->xt0[nb][DIN + j][r] = n;
        }
        __syncthreads();

        // ===== layer 1 gemm =====
        {
            float a1[M], a2[M], a3[M];
#pragma unroll
            for (int r = 0; r < M; ++r) { a1[r] = 0.f; a2[r] = 0.f; a3[r] = 0.f; }
            if (tid < 179) {                     // q0: rec [0,124)
                int j = tid;
                gemm_rec<NH1>(g_F1R1, g_F2R1, g_TA1, NIN1, j, 0, 124,
                              sm->xt1, a1, a2, a3);
                store_part(sm->P.p1[0][j], a1, a2, a3);
            } else if (tid < 358) {              // q1: rec [124,179) + ta-in [0,206)
                int j = tid - 179;
                gemm_rec<NH1>(g_F1R1, g_F2R1, g_TA1, NIN1, j, 124, 55,
                              sm->xt1, a1, a2, a3);
                gemm_ta<NH1>(g_TA1, j, 0, 206, sm->xt1, a3);
                store_part(sm->P.p1[1][j], a1, a2, a3);
            } else {                             // q2 (j<154): ta-in [206,269) + pk
                int j = tid - 358;
                if (j < 154) {
                    gemm_ta<NH1>(g_TA1, j, 206, 63, sm->xt1, a3);
                    gemm_pk<NH1>(g_P11, g_P21, g_PO1, j, 0, (int)sm->c1[j],
                                 &sm->xt1[0][0], a1, a2);
                    store_part(sm->P.p1[2][j], a1, a2, a3);
                }
                // L1 tail: j = 154..178, 5 pieces each, on tids 358..482
                int w = tid - 358;
                if (w < 125) {
                    int jx = w / 5, pc = w % 5;
                    int jt = 154 + jx;
                    float t1[M], t2[M], t3[M];
#pragma unroll
                    for (int r = 0; r < M; ++r) { t1[r] = 0.f; t2[r] = 0.f; t3[r] = 0.f; }
                    int slot;
                    if (pc == 0) {
                        gemm_ta<NH1>(g_TA1, jt, 206, 63, sm->xt1, t3);
                        slot = 2;
                    } else {
                        int cnt = (int)sm->c1[jt];
                        int s0 = 34 * (pc - 1);
                        int s1 = (pc == 4) ? cnt : min(34 * pc, cnt);
                        if (s1 < s0) s1 = s0;
                        gemm_pk<NH1>(g_P11, g_P21, g_PO1, jt, s0, s1,
                                     &sm->xt1[0][0], t1, t2);
                        slot = 2 + pc;
                    }
                    store_part(sm->P.p1[slot][jt], t1, t2, t3);
                }
            }
        }
        __syncthreads();

        // ===== layer 1 reduce + bias + activate =====
        for (int c = tid; c < NH1 * M; c += BT) {
            int j = c >> 3, r = c & 7;
            float f1 = sm->P.p1[0][j][0][r] + sm->P.p1[1][j][0][r] + sm->P.p1[2][j][0][r];
            float f2 = sm->P.p1[0][j][1][r] + sm->P.p1[1][j][1][r] + sm->P.p1[2][j][1][r];
            float g3 = sm->P.p1[0][j][2][r] + sm->P.p1[1][j][2][r] + sm->P.p1[2][j][2][r];
            if (j >= 154) {
#pragma unroll
                for (int sl = 3; sl < 7; ++sl) {
                    f1 += sm->P.p1[sl][j][0][r];
                    f2 += sm->P.p1[sl][j][1][r];
                    g3 += sm->P.p1[sl][j][2][r];
                }
            }
            f1 += sm->b1[j]; f2 += sm->b1[NH1 + j]; g3 += sm->b1[2 * NH1 + j];
            float n = cfc_cell(f1, f2, g3);
            sm->xt2[j][r] = n;
            sm->xt1[NH0 + j][r] = n;
        }
        __syncthreads();

        // ===== layer 2 gemm ===== 8 pieces per j, 512 units exactly
        {
            int j = tid & 63, pc = tid >> 6;
            float a1[M], a2[M], a3[M];
#pragma unroll
            for (int r = 0; r < M; ++r) { a1[r] = 0.f; a2[r] = 0.f; a3[r] = 0.f; }
            if (pc < 3) {                        // rec chunks 21/21/22
                int k0 = pc * 21, len = (pc == 2) ? 22 : 21;
                gemm_rec<NH2>(g_F1R2, g_F2R2, g_TA2, NIN2, j, k0, len,
                              sm->xt2, a1, a2, a3);
            } else if (pc < 6) {                 // ta-in chunks 60/60/59
                int q = pc - 3;
                int k0 = q * 60, len = (q == 2) ? 59 : 60;
                gemm_ta<NH2>(g_TA2, j, k0, len, sm->xt2, a3);
            } else {                             // pk halves [0,45),[45,cnt)
                int hf = pc - 6;
                int cnt = (int)sm->c2[j];
                int s0 = hf ? 45 : 0;
                int s1 = hf ? cnt : min(45, cnt);
                if (s1 < s0) s1 = s0;
                gemm_pk<NH2>(g_P12, g_P22, g_PO2, j, s0, s1,
                             &sm->xt2[0][0], a1, a2);
            }
            store_part(sm->P.p2[pc][j], a1, a2, a3);
        }
        __syncthreads();

        // ===== layer 2 reduce + bias + activate ===== 512 cells, 1/thread
        {
            int j = tid >> 3, r = tid & 7;
            float f1 = 0.f, f2 = 0.f, g3 = 0.f;
#pragma unroll
            for (int sl = 0; sl < 8; ++sl) {
                f1 += sm->P.p2[sl][j][0][r];
                f2 += sm->P.p2[sl][j][1][r];
                g3 += sm->P.p2[sl][j][2][r];
            }
            f1 += sm->b2[j]; f2 += sm->b2[NH2 + j]; g3 += sm->b2[2 * NH2 + j];
            sm->xt2[NH1 + j][r] = cfc_cell(f1, f2, g3);
        }
        __syncthreads();

        // ===== fused output projection + x(t+1) store =====
        {
            int r = tid >> 6, o = tid & 63;
            float a = sm->fcb[o];
#pragma unroll 8
            for (int mm = 0; mm < OUTD; ++mm)
                a += sm->fcT[mm * OUTD + o] * sm->xt2[NH1 + mm][r];
            out[((long long)(row0 + r) * Tsz + t) * OUTD + o] = a;
        }
        if (t + 1 < Tsz) {
            sm->xt0[nb][xc][xr]      = rx0;
            sm->xt0[nb][xc + 64][xr] = rx1;
        }
        __syncthreads();
    }

    // ---- final hidden state (Tsz even -> final h0 in buffer 0) ----
    float* hn = out + PRED_ELEMS;
    for (int i = tid; i < M * 512; i += BT) {
        int r = i >> 9, c = i & 511;
        float v;
        if (c < NH0)            v = sm->xt0[0][DIN + c][r];
        else if (c < NH0 + NH1) v = sm->xt1[c][r];
        else                    v = sm->xt2[NH1 + (c - NH0 - NH1)][r];
        hn[(long long)(row0 + r) * 512 + c] = v;
    }
}

// ---------------- host launcher ----------------
extern "C" void kernel_launch(void* const* d_in, const int* in_sizes, int n_in,
                              void* d_out, int out_size) {
    (void)n_in; (void)out_size;
    const float* x      = (const float*)d_in[0];
    const float* hidden = (const float*)d_in[1];
    const void*  m0     = d_in[2];
    const void*  m1     = d_in[3];
    const void*  m2     = d_in[4];
    const float* ff1_w0 = (const float*)d_in[5];
    const float* ff1_b0 = (const float*)d_in[6];
    const float* ff2_w0 = (const float*)d_in[7];
    const float* ff2_b0 = (const float*)d_in[8];
    const float* ta_w0  = (const float*)d_in[9];
    const float* ta_b0  = (const float*)d_in[10];
    const float* tb_w0  = (const float*)d_in[11];
    const float* tb_b0  = (const float*)d_in[12];
    const float* ff1_w1 = (const float*)d_in[13];
    const float* ff1_b1 = (const float*)d_in[14];
    const float* ff2_w1 = (const float*)d_in[15];
    const float* ff2_b1 = (const float*)d_in[16];
    const float* ta_w1  = (const float*)d_in[17];
    const float* ta_b1  = (const float*)d_in[18];
    const float* tb_w1  = (const float*)d_in[19];
    const float* tb_b1  = (const float*)d_in[20];
    const float* ff1_w2 = (const float*)d_in[21];
    const float* ff1_b2 = (const float*)d_in[22];
    const float* ff2_w2 = (const float*)d_in[23];
    const float* ff2_b2 = (const float*)d_in[24];
    const float* ta_w2  = (const float*)d_in[25];
    const float* ta_b2  = (const float*)d_in[26];
    const float* tb_w2  = (const float*)d_in[27];
    const float* tb_b2  = (const float*)d_in[28];
    const float* fc_w   = (const float*)d_in[29];
    const float* fc_b   = (const float*)d_in[30];
    float* out = (float*)d_out;

    detect_kernel<<<3, 256>>>(m0, in_sizes[2], m1, in_sizes[3], m2, in_sizes[4]);

    prep_dense<<<512, 256>>>(
        ff1_w0, ff2_w0, ta_w0, tb_w0, ff1_b0, ff2_b0, ta_b0, tb_b0,
        ff1_w1, ff2_w1, ta_w1, tb_w1, ff1_b1, ff2_b1, ta_b1, tb_b1,
        ff1_w2, ff2_w2, ta_w2, tb_w2, ff1_b2, ff2_b2, ta_b2, tb_b2);

    prep_pack<<<1, BT>>>(ff1_w0, ff2_w0, m0,
                         ff1_w1, ff2_w1, m1,
                         ff1_w2, ff2_w2, m2);

    cudaFuncSetAttribute(ncp_main, cudaFuncAttributeMaxDynamicSharedMemorySize,
                         (int)sizeof(SM));
    ncp_main<<<Bsz / M, BT, sizeof(SM)>>>(x, hidden, fc_w, fc_b, out);
}